// round 2
// baseline (speedup 1.0000x reference)
#include <cuda_runtime.h>
#include <cuda_bf16.h>
#include <math.h>

// Problem constants: B=4, S=1024, D=1024, H=16, Hd=64
#define PB 4
#define PS 1024
#define PD 1024
#define PH 16
#define PHD 64
#define BS (PB * PS)              // 4096 rows
#define QKV_N (3 * PD)            // 3072
#define ATTN_OUT_ELEMS (4194304ull)      // 4*1024*1024
#define ATTN_W_ELEMS   (67108864ull)     // 4*16*1024*1024

// Scratch (device globals: allocation-free rule)
__device__ float g_qkv[BS * QKV_N];          // 48 MB  [4096, 3072] row-major
__device__ float g_ctx[BS * PD];             // 16 MB  [4096, 1024] (B,S,H*Hd)
__device__ float g_wscratch[ATTN_W_ELEMS];   // 256 MB fallback if weights not in d_out

// ---------------------------------------------------------------------------
// K1/K5: generic SGEMM  C[M,N] = A[M,K] @ B[K,N] + bias[N]
// 128x128 block tile, BK=8, 256 threads, 8x8 per-thread
// ---------------------------------------------------------------------------
__global__ __launch_bounds__(256) void sgemm128(
    const float* __restrict__ A, const float* __restrict__ B,
    const float* __restrict__ bias, float* __restrict__ C,
    int M, int N, int K)
{
    __shared__ float As[8][128];
    __shared__ float Bsm[8][128];

    int tid = threadIdx.x;
    int tx = tid & 15;        // 0..15 -> col group (8 cols)
    int ty = tid >> 4;        // 0..15 -> row group (8 rows)
    int m0 = blockIdx.y * 128;
    int n0 = blockIdx.x * 128;

    const float* Ab = A + (size_t)m0 * K;
    const float* Bb = B + n0;

    float acc[8][8];
#pragma unroll
    for (int i = 0; i < 8; i++)
#pragma unroll
        for (int j = 0; j < 8; j++) acc[i][j] = 0.f;

    int arow = tid >> 1;            // 0..127
    int acol = (tid & 1) * 4;       // 0 or 4
    int bk = tid >> 5;              // 0..7
    int bn = (tid & 31) * 4;        // 0..124

    for (int k0 = 0; k0 < K; k0 += 8) {
        float4 av = *(const float4*)(Ab + (size_t)arow * K + k0 + acol);
        As[acol + 0][arow] = av.x;
        As[acol + 1][arow] = av.y;
        As[acol + 2][arow] = av.z;
        As[acol + 3][arow] = av.w;
        float4 bv = *(const float4*)(Bb + (size_t)(k0 + bk) * N + bn);
        *(float4*)&Bsm[bk][bn] = bv;
        __syncthreads();

#pragma unroll
        for (int kk = 0; kk < 8; kk++) {
            float a[8], b[8];
            *(float4*)(a)     = *(float4*)&As[kk][ty * 8];
            *(float4*)(a + 4) = *(float4*)&As[kk][ty * 8 + 4];
            *(float4*)(b)     = *(float4*)&Bsm[kk][tx * 8];
            *(float4*)(b + 4) = *(float4*)&Bsm[kk][tx * 8 + 4];
#pragma unroll
            for (int i = 0; i < 8; i++)
#pragma unroll
                for (int j = 0; j < 8; j++)
                    acc[i][j] = fmaf(a[i], b[j], acc[i][j]);
        }
        __syncthreads();
    }

    float bsv[8];
#pragma unroll
    for (int j = 0; j < 8; j++) bsv[j] = bias[n0 + tx * 8 + j];

#pragma unroll
    for (int i = 0; i < 8; i++) {
        int m = m0 + ty * 8 + i;
        float* Cr = C + (size_t)m * N + n0 + tx * 8;
        float4 o0, o1;
        o0.x = acc[i][0] + bsv[0]; o0.y = acc[i][1] + bsv[1];
        o0.z = acc[i][2] + bsv[2]; o0.w = acc[i][3] + bsv[3];
        o1.x = acc[i][4] + bsv[4]; o1.y = acc[i][5] + bsv[5];
        o1.z = acc[i][6] + bsv[6]; o1.w = acc[i][7] + bsv[7];
        *(float4*)(Cr)     = o0;
        *(float4*)(Cr + 4) = o1;
    }
}

// ---------------------------------------------------------------------------
// K2: scores[bh, q, k] = (Q[q,:] . K[k,:]) / 8  for causal blocks only
// Q element (b,h,s,d) = qkv[(b*1024+s)*3072 + h*64 + d]; K at +1024
// grid: (kblk=8, qblk=8, bh=64), 256 threads, 128x128 tile
// ---------------------------------------------------------------------------
__global__ __launch_bounds__(256) void scores_kernel(
    const float* __restrict__ qkv, float* __restrict__ w)
{
    if (blockIdx.x > blockIdx.y) return;   // strictly upper-tri block: never read

    __shared__ float Qs[128][17];
    __shared__ float Ks[128][17];

    int tid = threadIdx.x;
    int tx = tid & 15;
    int ty = tid >> 4;
    int bh = blockIdx.z;
    int b = bh >> 4, h = bh & 15;
    int q0 = blockIdx.y * 128;
    int k0r = blockIdx.x * 128;

    const float* Qb = qkv + (size_t)(b * PS + q0) * QKV_N + h * PHD;
    const float* Kb = qkv + (size_t)(b * PS + k0r) * QKV_N + PD + h * PHD;

    float acc[8][8];
#pragma unroll
    for (int i = 0; i < 8; i++)
#pragma unroll
        for (int j = 0; j < 8; j++) acc[i][j] = 0.f;

    for (int d0 = 0; d0 < PHD; d0 += 16) {
#pragma unroll
        for (int it = 0; it < 2; it++) {
            int idx = tid + it * 256;       // 0..511
            int r = idx >> 2;               // 0..127
            int c = (idx & 3) * 4;          // 0,4,8,12
            float4 qv = *(const float4*)(Qb + (size_t)r * QKV_N + d0 + c);
            Qs[r][c + 0] = qv.x; Qs[r][c + 1] = qv.y;
            Qs[r][c + 2] = qv.z; Qs[r][c + 3] = qv.w;
            float4 kv = *(const float4*)(Kb + (size_t)r * QKV_N + d0 + c);
            Ks[r][c + 0] = kv.x; Ks[r][c + 1] = kv.y;
            Ks[r][c + 2] = kv.z; Ks[r][c + 3] = kv.w;
        }
        __syncthreads();

#pragma unroll
        for (int kk = 0; kk < 16; kk++) {
            float a[8], bb[8];
#pragma unroll
            for (int i = 0; i < 8; i++) a[i] = Qs[ty * 8 + i][kk];
#pragma unroll
            for (int j = 0; j < 8; j++) bb[j] = Ks[tx * 8 + j][kk];
#pragma unroll
            for (int i = 0; i < 8; i++)
#pragma unroll
                for (int j = 0; j < 8; j++)
                    acc[i][j] = fmaf(a[i], bb[j], acc[i][j]);
        }
        __syncthreads();
    }

#pragma unroll
    for (int i = 0; i < 8; i++) {
        int q = q0 + ty * 8 + i;
        float* wr = w + ((size_t)bh * PS + q) * PS + k0r + tx * 8;
        float4 o0, o1;
        o0.x = acc[i][0] * 0.125f; o0.y = acc[i][1] * 0.125f;
        o0.z = acc[i][2] * 0.125f; o0.w = acc[i][3] * 0.125f;
        o1.x = acc[i][4] * 0.125f; o1.y = acc[i][5] * 0.125f;
        o1.z = acc[i][6] * 0.125f; o1.w = acc[i][7] * 0.125f;
        *(float4*)(wr)     = o0;
        *(float4*)(wr + 4) = o1;
    }
}

// ---------------------------------------------------------------------------
// K3: causal row softmax, in place. One block per row; writes zeros past diag.
// ---------------------------------------------------------------------------
__global__ __launch_bounds__(256) void softmax_kernel(float* __restrict__ w)
{
    __shared__ float red[256];
    int tid = threadIdx.x;
    int row = blockIdx.x;                 // 0..65535 = bh*1024 + q
    int q = row & (PS - 1);
    int L = q + 1;
    float* p = w + (size_t)row * PS;

    float m = -INFINITY;
    for (int j = tid; j < L; j += 256) m = fmaxf(m, p[j]);
    red[tid] = m;
    __syncthreads();
    for (int s = 128; s > 0; s >>= 1) {
        if (tid < s) red[tid] = fmaxf(red[tid], red[tid + s]);
        __syncthreads();
    }
    m = red[0];
    __syncthreads();

    float sum = 0.f;
    for (int j = tid; j < L; j += 256) sum += expf(p[j] - m);
    red[tid] = sum;
    __syncthreads();
    for (int s = 128; s > 0; s >>= 1) {
        if (tid < s) red[tid] += red[tid + s];
        __syncthreads();
    }
    float inv = 1.f / red[0];

    for (int j = tid; j < PS; j += 256)
        p[j] = (j < L) ? expf(p[j] - m) * inv : 0.f;
}

// ---------------------------------------------------------------------------
// K4: ctx[b, q, h*64+d] = sum_k W[bh,q,k] * V[b,k,h,d]
// grid: (qblk=8, bh=64), block computes 128 x 64, K truncated at causal edge
// ---------------------------------------------------------------------------
__global__ __launch_bounds__(256) void av_kernel(
    const float* __restrict__ w, const float* __restrict__ qkv,
    float* __restrict__ ctx)
{
    __shared__ float Ws[128][17];
    __shared__ float Vs[16][64];

    int tid = threadIdx.x;
    int tx = tid & 15;        // col group: tx*4
    int ty = tid >> 4;        // row group: ty*8
    int bh = blockIdx.y;
    int b = bh >> 4, h = bh & 15;
    int q0 = blockIdx.x * 128;

    const float* Wb = w + ((size_t)bh * PS + q0) * PS;
    const float* Vb = qkv + (size_t)b * PS * QKV_N + 2 * PD + h * PHD;

    float acc[8][4];
#pragma unroll
    for (int i = 0; i < 8; i++)
#pragma unroll
        for (int j = 0; j < 4; j++) acc[i][j] = 0.f;

    int kend = q0 + 128;      // weights are exact zeros past diag
    for (int k0 = 0; k0 < kend; k0 += 16) {
#pragma unroll
        for (int it = 0; it < 2; it++) {
            int idx = tid + it * 256;
            int r = idx >> 2;
            int c = (idx & 3) * 4;
            float4 wv = *(const float4*)(Wb + (size_t)r * PS + k0 + c);
            Ws[r][c + 0] = wv.x; Ws[r][c + 1] = wv.y;
            Ws[r][c + 2] = wv.z; Ws[r][c + 3] = wv.w;
        }
        {
            int r = tid >> 4;           // 0..15
            int c = (tid & 15) * 4;     // 0..60
            float4 vv = *(const float4*)(Vb + (size_t)(k0 + r) * QKV_N + c);
            *(float4*)&Vs[r][c] = vv;
        }
        __syncthreads();

#pragma unroll
        for (int kk = 0; kk < 16; kk++) {
            float a[8];
#pragma unroll
            for (int i = 0; i < 8; i++) a[i] = Ws[ty * 8 + i][kk];
            float4 bv = *(const float4*)&Vs[kk][tx * 4];
#pragma unroll
            for (int i = 0; i < 8; i++) {
                acc[i][0] = fmaf(a[i], bv.x, acc[i][0]);
                acc[i][1] = fmaf(a[i], bv.y, acc[i][1]);
                acc[i][2] = fmaf(a[i], bv.z, acc[i][2]);
                acc[i][3] = fmaf(a[i], bv.w, acc[i][3]);
            }
        }
        __syncthreads();
    }

#pragma unroll
    for (int i = 0; i < 8; i++) {
        int q = q0 + ty * 8 + i;
        float4 o;
        o.x = acc[i][0]; o.y = acc[i][1]; o.z = acc[i][2]; o.w = acc[i][3];
        *(float4*)(ctx + (size_t)(b * PS + q) * PD + h * PHD + tx * 4) = o;
    }
}

// ---------------------------------------------------------------------------
extern "C" void kernel_launch(void* const* d_in, const int* in_sizes, int n_in,
                              void* d_out, int out_size)
{
    const float* hidden = (const float*)d_in[0];   // [4,1024,1024]
    const float* W_attn = (const float*)d_in[1];   // [1024,3072]
    const float* b_attn = (const float*)d_in[2];   // [3072]
    const float* W_proj = (const float*)d_in[3];   // [1024,1024]
    const float* b_proj = (const float*)d_in[4];   // [1024]
    float* out = (float*)d_out;

    float *qkv, *ctx, *wscr;
    cudaGetSymbolAddress((void**)&qkv, g_qkv);
    cudaGetSymbolAddress((void**)&ctx, g_ctx);
    cudaGetSymbolAddress((void**)&wscr, g_wscratch);

    // Output layout: (attn_output, attn_weights) concatenated when both fit.
    float* attn_out = out;
    float* wptr;
    if ((unsigned long long)out_size >= ATTN_OUT_ELEMS + ATTN_W_ELEMS) {
        wptr = out + ATTN_OUT_ELEMS;
    } else if ((unsigned long long)out_size == ATTN_W_ELEMS) {
        wptr = out;            // weights-only output
        attn_out = ctx;        // sink (unused by checker then)
    } else {
        wptr = wscr;           // attn_output-only output
    }

    // K1: QKV projection  [4096,3072]
    sgemm128<<<dim3(QKV_N / 128, BS / 128), 256>>>(
        hidden, W_attn, b_attn, qkv, BS, QKV_N, PD);

    // K2: causal scores
    scores_kernel<<<dim3(PS / 128, PS / 128, PB * PH), 256>>>(qkv, wptr);

    // K3: softmax (writes the full attn_weights tensor, zeros above diag)
    softmax_kernel<<<PB * PH * PS, 256>>>(wptr);

    // K4: attn @ V -> ctx in [B,S,H*Hd] layout
    av_kernel<<<dim3(PS / 128, PB * PH), 256>>>(wptr, qkv, ctx);

    // K5: output projection
    sgemm128<<<dim3(PD / 128, BS / 128), 256>>>(
        ctx, W_proj, b_proj, attn_out, BS, PD, PD);
}

// round 3
// speedup vs baseline: 1.0936x; 1.0936x over previous
#include <cuda_runtime.h>
#include <cuda_bf16.h>
#include <math.h>

// Problem constants: B=4, S=1024, D=1024, H=16, Hd=64
#define PB 4
#define PS 1024
#define PD 1024
#define PH 16
#define PHD 64
#define BS (PB * PS)              // 4096 rows
#define QKV_N (3 * PD)            // 3072
#define ATTN_OUT_ELEMS (4194304ull)      // 4*1024*1024
#define ATTN_W_ELEMS   (67108864ull)     // 4*16*1024*1024

// Scratch (device globals: allocation-free rule)
__device__ float g_qkv[BS * QKV_N];          // 48 MB  [4096, 3072] row-major
__device__ float g_ctx[BS * PD];             // 16 MB  [4096, 1024]
__device__ float g_wscratch[ATTN_W_ELEMS];   // 256 MB fallback

// ---------------------------------------------------------------------------
// tf32 mma helpers
// ---------------------------------------------------------------------------
__device__ __forceinline__ unsigned f2tf32(float f) {
    unsigned u;
    asm("cvt.rna.tf32.f32 %0, %1;" : "=r"(u) : "f"(f));
    return u;
}

__device__ __forceinline__ void mma16n8k8(float c[4], const unsigned a[4],
                                          const unsigned b[2]) {
    asm volatile(
        "mma.sync.aligned.m16n8k8.row.col.f32.tf32.tf32.f32 "
        "{%0,%1,%2,%3}, {%4,%5,%6,%7}, {%8,%9}, {%0,%1,%2,%3};\n"
        : "+f"(c[0]), "+f"(c[1]), "+f"(c[2]), "+f"(c[3])
        : "r"(a[0]), "r"(a[1]), "r"(a[2]), "r"(a[3]),
          "r"(b[0]), "r"(b[1]));
}

// ---------------------------------------------------------------------------
// K1/K5: SGEMM via tf32 tensor cores. C[M,N] = A[M,K]@B[K,N] + bias
// 128x128 tile, BK=16, 256 threads (8 warps, 2x4), warp tile 64x32
// ---------------------------------------------------------------------------
__global__ __launch_bounds__(256) void sgemm_tf32(
    const float* __restrict__ A, const float* __restrict__ B,
    const float* __restrict__ bias, float* __restrict__ C,
    int M, int N, int K)
{
    __shared__ unsigned As[16][132];   // As[k][m]  (132 mod 32 == 4 -> cf frags)
    __shared__ unsigned Bs[16][132];   // Bs[k][n]

    int tid = threadIdx.x, lane = tid & 31, wid = tid >> 5;
    int wm = (wid >> 2) * 64, wn = (wid & 3) * 32;
    int m0 = blockIdx.y * 128, n0 = blockIdx.x * 128;
    int grp = lane >> 2, tig = lane & 3;

    float c[4][4][4];
#pragma unroll
    for (int mt = 0; mt < 4; mt++)
#pragma unroll
        for (int nt = 0; nt < 4; nt++)
#pragma unroll
            for (int i = 0; i < 4; i++) c[mt][nt][i] = 0.f;

    int ar = tid >> 1, ac = (tid & 1) * 8;     // A stage: row, col-base
    int bk = tid >> 4, bn = (tid & 15) * 8;    // B stage: k-row, n-base
    const float* Ap = A + (size_t)(m0 + ar) * K + ac;
    const float* Bp = B + (size_t)bk * N + n0 + bn;

    for (int k0 = 0; k0 < K; k0 += 16) {
        float4 a0 = *(const float4*)(Ap + k0);
        float4 a1 = *(const float4*)(Ap + k0 + 4);
        As[ac + 0][ar] = f2tf32(a0.x); As[ac + 1][ar] = f2tf32(a0.y);
        As[ac + 2][ar] = f2tf32(a0.z); As[ac + 3][ar] = f2tf32(a0.w);
        As[ac + 4][ar] = f2tf32(a1.x); As[ac + 5][ar] = f2tf32(a1.y);
        As[ac + 6][ar] = f2tf32(a1.z); As[ac + 7][ar] = f2tf32(a1.w);

        const float* bp = Bp + (size_t)k0 * N;
        float4 b0 = *(const float4*)(bp);
        float4 b1 = *(const float4*)(bp + 4);
        uint4 u0 = make_uint4(f2tf32(b0.x), f2tf32(b0.y), f2tf32(b0.z), f2tf32(b0.w));
        uint4 u1 = make_uint4(f2tf32(b1.x), f2tf32(b1.y), f2tf32(b1.z), f2tf32(b1.w));
        *(uint4*)&Bs[bk][bn]     = u0;
        *(uint4*)&Bs[bk][bn + 4] = u1;
        __syncthreads();

#pragma unroll
        for (int ks = 0; ks < 2; ks++) {
            int kb = ks * 8;
            unsigned af[4][4], bf[4][2];
#pragma unroll
            for (int mt = 0; mt < 4; mt++) {
                int row = wm + mt * 16 + grp;
                af[mt][0] = As[kb + tig][row];
                af[mt][1] = As[kb + tig][row + 8];
                af[mt][2] = As[kb + tig + 4][row];
                af[mt][3] = As[kb + tig + 4][row + 8];
            }
#pragma unroll
            for (int nt = 0; nt < 4; nt++) {
                int col = wn + nt * 8 + grp;
                bf[nt][0] = Bs[kb + tig][col];
                bf[nt][1] = Bs[kb + tig + 4][col];
            }
#pragma unroll
            for (int mt = 0; mt < 4; mt++)
#pragma unroll
                for (int nt = 0; nt < 4; nt++)
                    mma16n8k8(c[mt][nt], af[mt], bf[nt]);
        }
        __syncthreads();
    }

#pragma unroll
    for (int mt = 0; mt < 4; mt++) {
        int r0 = m0 + wm + mt * 16 + grp;
#pragma unroll
        for (int nt = 0; nt < 4; nt++) {
            int col = n0 + wn + nt * 8 + tig * 2;
            float2 bv = *(const float2*)(bias + col);
            float2 o0 = make_float2(c[mt][nt][0] + bv.x, c[mt][nt][1] + bv.y);
            float2 o1 = make_float2(c[mt][nt][2] + bv.x, c[mt][nt][3] + bv.y);
            *(float2*)(C + (size_t)r0 * N + col)       = o0;
            *(float2*)(C + (size_t)(r0 + 8) * N + col) = o1;
        }
    }
}

// ---------------------------------------------------------------------------
// K2: scores = Q.K^T / 8 via tf32 mma, causal blocks only
// grid: (kblk=8, qblk=8, bh=64)
// ---------------------------------------------------------------------------
__global__ __launch_bounds__(256) void scores_tf32(
    const float* __restrict__ qkv, float* __restrict__ w)
{
    if (blockIdx.x > blockIdx.y) return;

    __shared__ unsigned As[16][132];   // Q^T: As[d][q]
    __shared__ unsigned Bs[16][132];   // K^T: Bs[d][k]

    int tid = threadIdx.x, lane = tid & 31, wid = tid >> 5;
    int wm = (wid >> 2) * 64, wn = (wid & 3) * 32;
    int grp = lane >> 2, tig = lane & 3;
    int bh = blockIdx.z;
    int b = bh >> 4, h = bh & 15;
    int q0 = blockIdx.y * 128;
    int k0r = blockIdx.x * 128;

    const float* Qb = qkv + (size_t)(b * PS + q0) * QKV_N + h * PHD;
    const float* Kb = qkv + (size_t)(b * PS + k0r) * QKV_N + PD + h * PHD;

    float c[4][4][4];
#pragma unroll
    for (int mt = 0; mt < 4; mt++)
#pragma unroll
        for (int nt = 0; nt < 4; nt++)
#pragma unroll
            for (int i = 0; i < 4; i++) c[mt][nt][i] = 0.f;

    int ar = tid >> 1, ac = (tid & 1) * 8;

    for (int d0 = 0; d0 < PHD; d0 += 16) {
        float4 q4a = *(const float4*)(Qb + (size_t)ar * QKV_N + d0 + ac);
        float4 q4b = *(const float4*)(Qb + (size_t)ar * QKV_N + d0 + ac + 4);
        As[ac + 0][ar] = f2tf32(q4a.x); As[ac + 1][ar] = f2tf32(q4a.y);
        As[ac + 2][ar] = f2tf32(q4a.z); As[ac + 3][ar] = f2tf32(q4a.w);
        As[ac + 4][ar] = f2tf32(q4b.x); As[ac + 5][ar] = f2tf32(q4b.y);
        As[ac + 6][ar] = f2tf32(q4b.z); As[ac + 7][ar] = f2tf32(q4b.w);
        float4 k4a = *(const float4*)(Kb + (size_t)ar * QKV_N + d0 + ac);
        float4 k4b = *(const float4*)(Kb + (size_t)ar * QKV_N + d0 + ac + 4);
        Bs[ac + 0][ar] = f2tf32(k4a.x); Bs[ac + 1][ar] = f2tf32(k4a.y);
        Bs[ac + 2][ar] = f2tf32(k4a.z); Bs[ac + 3][ar] = f2tf32(k4a.w);
        Bs[ac + 4][ar] = f2tf32(k4b.x); Bs[ac + 5][ar] = f2tf32(k4b.y);
        Bs[ac + 6][ar] = f2tf32(k4b.z); Bs[ac + 7][ar] = f2tf32(k4b.w);
        __syncthreads();

#pragma unroll
        for (int ks = 0; ks < 2; ks++) {
            int kb = ks * 8;
            unsigned af[4][4], bf[4][2];
#pragma unroll
            for (int mt = 0; mt < 4; mt++) {
                int row = wm + mt * 16 + grp;
                af[mt][0] = As[kb + tig][row];
                af[mt][1] = As[kb + tig][row + 8];
                af[mt][2] = As[kb + tig + 4][row];
                af[mt][3] = As[kb + tig + 4][row + 8];
            }
#pragma unroll
            for (int nt = 0; nt < 4; nt++) {
                int col = wn + nt * 8 + grp;
                bf[nt][0] = Bs[kb + tig][col];
                bf[nt][1] = Bs[kb + tig + 4][col];
            }
#pragma unroll
            for (int mt = 0; mt < 4; mt++)
#pragma unroll
                for (int nt = 0; nt < 4; nt++)
                    mma16n8k8(c[mt][nt], af[mt], bf[nt]);
        }
        __syncthreads();
    }

#pragma unroll
    for (int mt = 0; mt < 4; mt++) {
        int q = q0 + wm + mt * 16 + grp;
#pragma unroll
        for (int nt = 0; nt < 4; nt++) {
            int col = k0r + wn + nt * 8 + tig * 2;
            float* w0 = w + ((size_t)bh * PS + q) * PS + col;
            float* w1 = w + ((size_t)bh * PS + q + 8) * PS + col;
            *(float2*)w0 = make_float2(c[mt][nt][0] * 0.125f, c[mt][nt][1] * 0.125f);
            *(float2*)w1 = make_float2(c[mt][nt][2] * 0.125f, c[mt][nt][3] * 0.125f);
        }
    }
}

// ---------------------------------------------------------------------------
// K3: causal row softmax, in place (zeros past diag)
// ---------------------------------------------------------------------------
__global__ __launch_bounds__(256) void softmax_kernel(float* __restrict__ w)
{
    __shared__ float red[256];
    int tid = threadIdx.x;
    int row = blockIdx.x;
    int q = row & (PS - 1);
    int L = q + 1;
    float* p = w + (size_t)row * PS;

    float m = -INFINITY;
    for (int j = tid; j < L; j += 256) m = fmaxf(m, p[j]);
    red[tid] = m;
    __syncthreads();
    for (int s = 128; s > 0; s >>= 1) {
        if (tid < s) red[tid] = fmaxf(red[tid], red[tid + s]);
        __syncthreads();
    }
    m = red[0];
    __syncthreads();

    float sum = 0.f;
    for (int j = tid; j < L; j += 256) sum += expf(p[j] - m);
    red[tid] = sum;
    __syncthreads();
    for (int s = 128; s > 0; s >>= 1) {
        if (tid < s) red[tid] += red[tid + s];
        __syncthreads();
    }
    float inv = 1.f / red[0];

    for (int j = tid; j < PS; j += 256)
        p[j] = (j < L) ? expf(p[j] - m) * inv : 0.f;
}

// ---------------------------------------------------------------------------
// K4: ctx = attn_weights @ V via tf32 mma
// tile 128(q) x 64(d), warp tile 64x16, K truncated at causal edge
// ---------------------------------------------------------------------------
__global__ __launch_bounds__(256) void av_tf32(
    const float* __restrict__ w, const float* __restrict__ qkv,
    float* __restrict__ ctx)
{
    __shared__ unsigned As[16][132];   // W^T: As[k][q]
    __shared__ unsigned Bs[16][68];    // V:   Bs[k][d]

    int tid = threadIdx.x, lane = tid & 31, wid = tid >> 5;
    int wm = (wid >> 2) * 64, wn = (wid & 3) * 16;
    int grp = lane >> 2, tig = lane & 3;
    int bh = blockIdx.y;
    int b = bh >> 4, h = bh & 15;
    int q0 = blockIdx.x * 128;

    const float* Wb = w + ((size_t)bh * PS + q0) * PS;
    const float* Vb = qkv + (size_t)b * PS * QKV_N + 2 * PD + h * PHD;

    float c[4][2][4];
#pragma unroll
    for (int mt = 0; mt < 4; mt++)
#pragma unroll
        for (int nt = 0; nt < 2; nt++)
#pragma unroll
            for (int i = 0; i < 4; i++) c[mt][nt][i] = 0.f;

    int ar = tid >> 1, ac = (tid & 1) * 8;
    int vk = tid >> 4, vn = (tid & 15) * 4;
    int kend = q0 + 128;   // weights exactly zero past diagonal

    for (int k0 = 0; k0 < kend; k0 += 16) {
        float4 a0 = *(const float4*)(Wb + (size_t)ar * PS + k0 + ac);
        float4 a1 = *(const float4*)(Wb + (size_t)ar * PS + k0 + ac + 4);
        As[ac + 0][ar] = f2tf32(a0.x); As[ac + 1][ar] = f2tf32(a0.y);
        As[ac + 2][ar] = f2tf32(a0.z); As[ac + 3][ar] = f2tf32(a0.w);
        As[ac + 4][ar] = f2tf32(a1.x); As[ac + 5][ar] = f2tf32(a1.y);
        As[ac + 6][ar] = f2tf32(a1.z); As[ac + 7][ar] = f2tf32(a1.w);
        float4 vv = *(const float4*)(Vb + (size_t)(k0 + vk) * QKV_N + vn);
        uint4 uv = make_uint4(f2tf32(vv.x), f2tf32(vv.y), f2tf32(vv.z), f2tf32(vv.w));
        *(uint4*)&Bs[vk][vn] = uv;
        __syncthreads();

#pragma unroll
        for (int ks = 0; ks < 2; ks++) {
            int kb = ks * 8;
            unsigned af[4][4], bf[2][2];
#pragma unroll
            for (int mt = 0; mt < 4; mt++) {
                int row = wm + mt * 16 + grp;
                af[mt][0] = As[kb + tig][row];
                af[mt][1] = As[kb + tig][row + 8];
                af[mt][2] = As[kb + tig + 4][row];
                af[mt][3] = As[kb + tig + 4][row + 8];
            }
#pragma unroll
            for (int nt = 0; nt < 2; nt++) {
                int col = wn + nt * 8 + grp;
                bf[nt][0] = Bs[kb + tig][col];
                bf[nt][1] = Bs[kb + tig + 4][col];
            }
#pragma unroll
            for (int mt = 0; mt < 4; mt++)
#pragma unroll
                for (int nt = 0; nt < 2; nt++)
                    mma16n8k8(c[mt][nt], af[mt], bf[nt]);
        }
        __syncthreads();
    }

#pragma unroll
    for (int mt = 0; mt < 4; mt++) {
        int q = q0 + wm + mt * 16 + grp;
        float* c0 = ctx + (size_t)(b * PS + q) * PD + h * PHD;
        float* c1 = ctx + (size_t)(b * PS + q + 8) * PD + h * PHD;
#pragma unroll
        for (int nt = 0; nt < 2; nt++) {
            int col = wn + nt * 8 + tig * 2;
            *(float2*)(c0 + col) = make_float2(c[mt][nt][0], c[mt][nt][1]);
            *(float2*)(c1 + col) = make_float2(c[mt][nt][2], c[mt][nt][3]);
        }
    }
}

// ---------------------------------------------------------------------------
extern "C" void kernel_launch(void* const* d_in, const int* in_sizes, int n_in,
                              void* d_out, int out_size)
{
    const float* hidden = (const float*)d_in[0];
    const float* W_attn = (const float*)d_in[1];
    const float* b_attn = (const float*)d_in[2];
    const float* W_proj = (const float*)d_in[3];
    const float* b_proj = (const float*)d_in[4];
    float* out = (float*)d_out;

    float *qkv, *ctx, *wscr;
    cudaGetSymbolAddress((void**)&qkv, g_qkv);
    cudaGetSymbolAddress((void**)&ctx, g_ctx);
    cudaGetSymbolAddress((void**)&wscr, g_wscratch);

    float* attn_out = out;
    float* wptr;
    if ((unsigned long long)out_size >= ATTN_OUT_ELEMS + ATTN_W_ELEMS) {
        wptr = out + ATTN_OUT_ELEMS;
    } else if ((unsigned long long)out_size == ATTN_W_ELEMS) {
        wptr = out;
        attn_out = ctx;
    } else {
        wptr = wscr;
    }

    // K1: QKV projection
    sgemm_tf32<<<dim3(QKV_N / 128, BS / 128), 256>>>(
        hidden, W_attn, b_attn, qkv, BS, QKV_N, PD);

    // K2: causal scores
    scores_tf32<<<dim3(PS / 128, PS / 128, PB * PH), 256>>>(qkv, wptr);

    // K3: softmax
    softmax_kernel<<<PB * PH * PS, 256>>>(wptr);

    // K4: attn @ V
    av_tf32<<<dim3(PS / 128, PB * PH), 256>>>(wptr, qkv, ctx);

    // K5: output projection
    sgemm_tf32<<<dim3(PD / 128, BS / 128), 256>>>(
        ctx, W_proj, b_proj, attn_out, BS, PD, PD);
}

// round 4
// speedup vs baseline: 2.0959x; 1.9166x over previous
#include <cuda_runtime.h>
#include <cuda_bf16.h>
#include <math.h>

// Problem constants: B=4, S=1024, D=1024, H=16, Hd=64
#define PB 4
#define PS 1024
#define PD 1024
#define PH 16
#define PHD 64
#define BS (PB * PS)
#define QKV_N (3 * PD)
#define ATTN_OUT_ELEMS (4194304ull)
#define ATTN_W_ELEMS   (67108864ull)

__device__ float g_qkv[BS * QKV_N];
__device__ float g_ctx[BS * PD];
__device__ float g_wscratch[ATTN_W_ELEMS];

__device__ __forceinline__ unsigned f2tf32(float f) {
    unsigned u;
    asm("cvt.rna.tf32.f32 %0, %1;" : "=r"(u) : "f"(f));
    return u;
}

__device__ __forceinline__ void mma16n8k8(float c[4], const unsigned a[4],
                                          const unsigned b[2]) {
    asm volatile(
        "mma.sync.aligned.m16n8k8.row.col.f32.tf32.tf32.f32 "
        "{%0,%1,%2,%3}, {%4,%5,%6,%7}, {%8,%9}, {%0,%1,%2,%3};\n"
        : "+f"(c[0]), "+f"(c[1]), "+f"(c[2]), "+f"(c[3])
        : "r"(a[0]), "r"(a[1]), "r"(a[2]), "r"(a[3]),
          "r"(b[0]), "r"(b[1]));
}

// ---------------------------------------------------------------------------
// K1/K5: SGEMM tf32, 128x128 tile, BK=16, register-prefetch pipelined
// ---------------------------------------------------------------------------
__global__ __launch_bounds__(256) void sgemm_tf32(
    const float* __restrict__ A, const float* __restrict__ B,
    const float* __restrict__ bias, float* __restrict__ C,
    int M, int N, int K)
{
    __shared__ unsigned As[16][132];   // [k][m]
    __shared__ unsigned Bs[16][132];   // [k][n]

    int tid = threadIdx.x, lane = tid & 31, wid = tid >> 5;
    int wm = (wid >> 2) * 64, wn = (wid & 3) * 32;
    int m0 = blockIdx.y * 128, n0 = blockIdx.x * 128;
    int grp = lane >> 2, tig = lane & 3;

    float c[4][4][4];
#pragma unroll
    for (int mt = 0; mt < 4; mt++)
#pragma unroll
        for (int nt = 0; nt < 4; nt++)
#pragma unroll
            for (int i = 0; i < 4; i++) c[mt][nt][i] = 0.f;

    int ar = tid >> 1, ac = (tid & 1) * 8;
    int bk = tid >> 4, bn = (tid & 15) * 8;
    const float* Ap = A + (size_t)(m0 + ar) * K + ac;
    const float* Bp = B + (size_t)bk * N + n0 + bn;

    float4 pa0 = *(const float4*)(Ap);
    float4 pa1 = *(const float4*)(Ap + 4);
    float4 pb0 = *(const float4*)(Bp);
    float4 pb1 = *(const float4*)(Bp + 4);

    for (int k0 = 0; k0 < K; k0 += 16) {
        As[ac + 0][ar] = f2tf32(pa0.x); As[ac + 1][ar] = f2tf32(pa0.y);
        As[ac + 2][ar] = f2tf32(pa0.z); As[ac + 3][ar] = f2tf32(pa0.w);
        As[ac + 4][ar] = f2tf32(pa1.x); As[ac + 5][ar] = f2tf32(pa1.y);
        As[ac + 6][ar] = f2tf32(pa1.z); As[ac + 7][ar] = f2tf32(pa1.w);
        uint4 u0 = make_uint4(f2tf32(pb0.x), f2tf32(pb0.y), f2tf32(pb0.z), f2tf32(pb0.w));
        uint4 u1 = make_uint4(f2tf32(pb1.x), f2tf32(pb1.y), f2tf32(pb1.z), f2tf32(pb1.w));
        *(uint4*)&Bs[bk][bn]     = u0;
        *(uint4*)&Bs[bk][bn + 4] = u1;
        __syncthreads();

        if (k0 + 16 < K) {   // prefetch next tile; overlaps mma below
            pa0 = *(const float4*)(Ap + k0 + 16);
            pa1 = *(const float4*)(Ap + k0 + 20);
            const float* bp = Bp + (size_t)(k0 + 16) * N;
            pb0 = *(const float4*)(bp);
            pb1 = *(const float4*)(bp + 4);
        }

#pragma unroll
        for (int ks = 0; ks < 2; ks++) {
            int kb = ks * 8;
            unsigned af[4][4], bf[4][2];
#pragma unroll
            for (int mt = 0; mt < 4; mt++) {
                int row = wm + mt * 16 + grp;
                af[mt][0] = As[kb + tig][row];
                af[mt][1] = As[kb + tig][row + 8];
                af[mt][2] = As[kb + tig + 4][row];
                af[mt][3] = As[kb + tig + 4][row + 8];
            }
#pragma unroll
            for (int nt = 0; nt < 4; nt++) {
                int col = wn + nt * 8 + grp;
                bf[nt][0] = Bs[kb + tig][col];
                bf[nt][1] = Bs[kb + tig + 4][col];
            }
#pragma unroll
            for (int mt = 0; mt < 4; mt++)
#pragma unroll
                for (int nt = 0; nt < 4; nt++)
                    mma16n8k8(c[mt][nt], af[mt], bf[nt]);
        }
        __syncthreads();
    }

#pragma unroll
    for (int mt = 0; mt < 4; mt++) {
        int r0 = m0 + wm + mt * 16 + grp;
#pragma unroll
        for (int nt = 0; nt < 4; nt++) {
            int col = n0 + wn + nt * 8 + tig * 2;
            float2 bv = *(const float2*)(bias + col);
            *(float2*)(C + (size_t)r0 * N + col) =
                make_float2(c[mt][nt][0] + bv.x, c[mt][nt][1] + bv.y);
            *(float2*)(C + (size_t)(r0 + 8) * N + col) =
                make_float2(c[mt][nt][2] + bv.x, c[mt][nt][3] + bv.y);
        }
    }
}

// ---------------------------------------------------------------------------
// K2: scores = Q.K^T/8, causal blocks. Tiles staged in [row][d] layout,
// two d-chunks of 32, conflict-free fragment reads.
// ---------------------------------------------------------------------------
__global__ __launch_bounds__(256) void scores_tf32(
    const float* __restrict__ qkv, float* __restrict__ w)
{
    if (blockIdx.x > blockIdx.y) return;

    __shared__ unsigned Qs[128][36];   // [q][d-chunk]
    __shared__ unsigned Ks[128][36];   // [k][d-chunk]

    int tid = threadIdx.x, lane = tid & 31, wid = tid >> 5;
    int wm = (wid >> 2) * 64, wn = (wid & 3) * 32;
    int grp = lane >> 2, tig = lane & 3;
    int bh = blockIdx.z;
    int b = bh >> 4, h = bh & 15;
    int q0 = blockIdx.y * 128;
    int k0r = blockIdx.x * 128;

    const float* Qb = qkv + (size_t)(b * PS + q0) * QKV_N + h * PHD;
    const float* Kb = qkv + (size_t)(b * PS + k0r) * QKV_N + PD + h * PHD;

    float c[4][4][4];
#pragma unroll
    for (int mt = 0; mt < 4; mt++)
#pragma unroll
        for (int nt = 0; nt < 4; nt++)
#pragma unroll
            for (int i = 0; i < 4; i++) c[mt][nt][i] = 0.f;

    int lr = tid >> 1, lc = (tid & 1) * 16;  // 16 floats per thread per tensor

#pragma unroll
    for (int chunk = 0; chunk < 2; chunk++) {
        int d0 = chunk * 32;
#pragma unroll
        for (int i = 0; i < 4; i++) {
            float4 qv = *(const float4*)(Qb + (size_t)lr * QKV_N + d0 + lc + i * 4);
            float4 kv = *(const float4*)(Kb + (size_t)lr * QKV_N + d0 + lc + i * 4);
            Qs[lr][lc + i * 4 + 0] = f2tf32(qv.x); Qs[lr][lc + i * 4 + 1] = f2tf32(qv.y);
            Qs[lr][lc + i * 4 + 2] = f2tf32(qv.z); Qs[lr][lc + i * 4 + 3] = f2tf32(qv.w);
            Ks[lr][lc + i * 4 + 0] = f2tf32(kv.x); Ks[lr][lc + i * 4 + 1] = f2tf32(kv.y);
            Ks[lr][lc + i * 4 + 2] = f2tf32(kv.z); Ks[lr][lc + i * 4 + 3] = f2tf32(kv.w);
        }
        __syncthreads();

#pragma unroll
        for (int ks = 0; ks < 4; ks++) {
            int kb = ks * 8;
            unsigned af[4][4], bf[4][2];
#pragma unroll
            for (int mt = 0; mt < 4; mt++) {
                int row = wm + mt * 16 + grp;
                af[mt][0] = Qs[row][kb + tig];
                af[mt][1] = Qs[row + 8][kb + tig];
                af[mt][2] = Qs[row][kb + tig + 4];
                af[mt][3] = Qs[row + 8][kb + tig + 4];
            }
#pragma unroll
            for (int nt = 0; nt < 4; nt++) {
                int col = wn + nt * 8 + grp;
                bf[nt][0] = Ks[col][kb + tig];
                bf[nt][1] = Ks[col][kb + tig + 4];
            }
#pragma unroll
            for (int mt = 0; mt < 4; mt++)
#pragma unroll
                for (int nt = 0; nt < 4; nt++)
                    mma16n8k8(c[mt][nt], af[mt], bf[nt]);
        }
        __syncthreads();
    }

#pragma unroll
    for (int mt = 0; mt < 4; mt++) {
        int q = q0 + wm + mt * 16 + grp;
#pragma unroll
        for (int nt = 0; nt < 4; nt++) {
            int col = k0r + wn + nt * 8 + tig * 2;
            float* w0 = w + ((size_t)bh * PS + q) * PS + col;
            float* w1 = w + ((size_t)bh * PS + q + 8) * PS + col;
            *(float2*)w0 = make_float2(c[mt][nt][0] * 0.125f, c[mt][nt][1] * 0.125f);
            *(float2*)w1 = make_float2(c[mt][nt][2] * 0.125f, c[mt][nt][3] * 0.125f);
        }
    }
}

// ---------------------------------------------------------------------------
// K3: causal row softmax, register-resident. 1 block/row, 256 thr x float4.
// ---------------------------------------------------------------------------
__global__ __launch_bounds__(256) void softmax_kernel(float* __restrict__ w)
{
    __shared__ float red[16];
    int tid = threadIdx.x, lane = tid & 31, wid = tid >> 5;
    int row = blockIdx.x;
    int q = row & (PS - 1);
    int L = q + 1;
    float* p = w + (size_t)row * PS;

    float4 v = *(float4*)(p + tid * 4);
    float x[4] = {v.x, v.y, v.z, v.w};
    int j0 = tid * 4;
#pragma unroll
    for (int i = 0; i < 4; i++)
        if (j0 + i >= L) x[i] = -INFINITY;

    float m = fmaxf(fmaxf(x[0], x[1]), fmaxf(x[2], x[3]));
#pragma unroll
    for (int s = 16; s > 0; s >>= 1)
        m = fmaxf(m, __shfl_xor_sync(0xffffffffu, m, s));
    if (lane == 0) red[wid] = m;
    __syncthreads();
    m = red[0];
#pragma unroll
    for (int i = 1; i < 8; i++) m = fmaxf(m, red[i]);

    float s = 0.f;
#pragma unroll
    for (int i = 0; i < 4; i++) {
        x[i] = __expf(x[i] - m);     // -inf -> 0
        s += x[i];
    }
#pragma unroll
    for (int sh = 16; sh > 0; sh >>= 1)
        s += __shfl_xor_sync(0xffffffffu, s, sh);
    if (lane == 0) red[8 + wid] = s;
    __syncthreads();
    s = red[8];
#pragma unroll
    for (int i = 1; i < 8; i++) s += red[8 + i];
    float inv = 1.f / s;

    *(float4*)(p + tid * 4) =
        make_float4(x[0] * inv, x[1] * inv, x[2] * inv, x[3] * inv);
}

// ---------------------------------------------------------------------------
// K4: ctx = attn @ V, BK=32, register-prefetch pipelined
// ---------------------------------------------------------------------------
__global__ __launch_bounds__(256) void av_tf32(
    const float* __restrict__ w, const float* __restrict__ qkv,
    float* __restrict__ ctx)
{
    __shared__ unsigned Ws[128][36];   // [q][k-chunk]
    __shared__ unsigned Vs[32][68];    // [k][d]

    int tid = threadIdx.x, lane = tid & 31, wid = tid >> 5;
    int wm = (wid >> 2) * 64, wn = (wid & 3) * 16;
    int grp = lane >> 2, tig = lane & 3;
    int bh = blockIdx.y;
    int b = bh >> 4, h = bh & 15;
    int q0 = blockIdx.x * 128;

    const float* Wb = w + ((size_t)bh * PS + q0) * PS;
    const float* Vb = qkv + (size_t)b * PS * QKV_N + 2 * PD + h * PHD;

    float c[4][2][4];
#pragma unroll
    for (int mt = 0; mt < 4; mt++)
#pragma unroll
        for (int nt = 0; nt < 2; nt++)
#pragma unroll
            for (int i = 0; i < 4; i++) c[mt][nt][i] = 0.f;

    int wr = tid >> 1, wc = (tid & 1) * 16;   // W: 16 floats/thread
    int vr = tid >> 3, vc = (tid & 7) * 8;    // V: 8 floats/thread
    int kend = q0 + 128;

    float4 pw[4], pv[2];
#pragma unroll
    for (int i = 0; i < 4; i++)
        pw[i] = *(const float4*)(Wb + (size_t)wr * PS + wc + i * 4);
#pragma unroll
    for (int i = 0; i < 2; i++)
        pv[i] = *(const float4*)(Vb + (size_t)vr * QKV_N + vc + i * 4);

    for (int k0 = 0; k0 < kend; k0 += 32) {
#pragma unroll
        for (int i = 0; i < 4; i++) {
            Ws[wr][wc + i * 4 + 0] = f2tf32(pw[i].x);
            Ws[wr][wc + i * 4 + 1] = f2tf32(pw[i].y);
            Ws[wr][wc + i * 4 + 2] = f2tf32(pw[i].z);
            Ws[wr][wc + i * 4 + 3] = f2tf32(pw[i].w);
        }
#pragma unroll
        for (int i = 0; i < 2; i++) {
            uint4 uv = make_uint4(f2tf32(pv[i].x), f2tf32(pv[i].y),
                                  f2tf32(pv[i].z), f2tf32(pv[i].w));
            *(uint4*)&Vs[vr][vc + i * 4] = uv;
        }
        __syncthreads();

        if (k0 + 32 < kend) {   // prefetch next tiles
#pragma unroll
            for (int i = 0; i < 4; i++)
                pw[i] = *(const float4*)(Wb + (size_t)wr * PS + k0 + 32 + wc + i * 4);
#pragma unroll
            for (int i = 0; i < 2; i++)
                pv[i] = *(const float4*)(Vb + (size_t)(k0 + 32 + vr) * QKV_N + vc + i * 4);
        }

#pragma unroll
        for (int ks = 0; ks < 4; ks++) {
            int kb = ks * 8;
            unsigned af[4][4], bf[2][2];
#pragma unroll
            for (int mt = 0; mt < 4; mt++) {
                int row = wm + mt * 16 + grp;
                af[mt][0] = Ws[row][kb + tig];
                af[mt][1] = Ws[row + 8][kb + tig];
                af[mt][2] = Ws[row][kb + tig + 4];
                af[mt][3] = Ws[row + 8][kb + tig + 4];
            }
#pragma unroll
            for (int nt = 0; nt < 2; nt++) {
                int col = wn + nt * 8 + grp;
                bf[nt][0] = Vs[kb + tig][col];
                bf[nt][1] = Vs[kb + tig + 4][col];
            }
#pragma unroll
            for (int mt = 0; mt < 4; mt++)
#pragma unroll
                for (int nt = 0; nt < 2; nt++)
                    mma16n8k8(c[mt][nt], af[mt], bf[nt]);
        }
        __syncthreads();
    }

#pragma unroll
    for (int mt = 0; mt < 4; mt++) {
        int q = q0 + wm + mt * 16 + grp;
        float* c0 = ctx + (size_t)(b * PS + q) * PD + h * PHD;
        float* c1 = ctx + (size_t)(b * PS + q + 8) * PD + h * PHD;
#pragma unroll
        for (int nt = 0; nt < 2; nt++) {
            int col = wn + nt * 8 + tig * 2;
            *(float2*)(c0 + col) = make_float2(c[mt][nt][0], c[mt][nt][1]);
            *(float2*)(c1 + col) = make_float2(c[mt][nt][2], c[mt][nt][3]);
        }
    }
}

// ---------------------------------------------------------------------------
extern "C" void kernel_launch(void* const* d_in, const int* in_sizes, int n_in,
                              void* d_out, int out_size)
{
    const float* hidden = (const float*)d_in[0];
    const float* W_attn = (const float*)d_in[1];
    const float* b_attn = (const float*)d_in[2];
    const float* W_proj = (const float*)d_in[3];
    const float* b_proj = (const float*)d_in[4];
    float* out = (float*)d_out;

    float *qkv, *ctx, *wscr;
    cudaGetSymbolAddress((void**)&qkv, g_qkv);
    cudaGetSymbolAddress((void**)&ctx, g_ctx);
    cudaGetSymbolAddress((void**)&wscr, g_wscratch);

    float* attn_out = out;
    float* wptr;
    if ((unsigned long long)out_size >= ATTN_OUT_ELEMS + ATTN_W_ELEMS) {
        wptr = out + ATTN_OUT_ELEMS;
    } else if ((unsigned long long)out_size == ATTN_W_ELEMS) {
        wptr = out;
        attn_out = ctx;
    } else {
        wptr = wscr;
    }

    sgemm_tf32<<<dim3(QKV_N / 128, BS / 128), 256>>>(
        hidden, W_attn, b_attn, qkv, BS, QKV_N, PD);

    scores_tf32<<<dim3(PS / 128, PS / 128, PB * PH), 256>>>(qkv, wptr);

    softmax_kernel<<<PB * PH * PS, 256>>>(wptr);

    av_tf32<<<dim3(PS / 128, PB * PH), 256>>>(wptr, qkv, ctx);

    sgemm_tf32<<<dim3(PD / 128, BS / 128), 256>>>(
        ctx, W_proj, b_proj, attn_out, BS, PD, PD);
}

// round 5
// speedup vs baseline: 2.2595x; 1.0781x over previous
#include <cuda_runtime.h>
#include <cuda_bf16.h>
#include <math.h>

// Problem constants: B=4, S=1024, D=1024, H=16, Hd=64
#define PB 4
#define PS 1024
#define PD 1024
#define PH 16
#define PHD 64
#define BS (PB * PS)
#define QKV_N (3 * PD)
#define ATTN_OUT_ELEMS (4194304ull)
#define ATTN_W_ELEMS   (67108864ull)

__device__ float g_qkv[BS * QKV_N];
__device__ float g_ctx[BS * PD];
__device__ float g_wscratch[ATTN_W_ELEMS];

__device__ __forceinline__ unsigned f2tf32(float f) {
    unsigned u;
    asm("cvt.rna.tf32.f32 %0, %1;" : "=r"(u) : "f"(f));
    return u;
}

__device__ __forceinline__ void mma16n8k8(float c[4], const unsigned a[4],
                                          const unsigned b[2]) {
    asm volatile(
        "mma.sync.aligned.m16n8k8.row.col.f32.tf32.tf32.f32 "
        "{%0,%1,%2,%3}, {%4,%5,%6,%7}, {%8,%9}, {%0,%1,%2,%3};\n"
        : "+f"(c[0]), "+f"(c[1]), "+f"(c[2]), "+f"(c[3])
        : "r"(a[0]), "r"(a[1]), "r"(a[2]), "r"(a[3]),
          "r"(b[0]), "r"(b[1]));
}

__device__ __forceinline__ float qmax(float v) {
    v = fmaxf(v, __shfl_xor_sync(0xffffffffu, v, 1));
    v = fmaxf(v, __shfl_xor_sync(0xffffffffu, v, 2));
    return v;
}
__device__ __forceinline__ float qsum(float v) {
    v += __shfl_xor_sync(0xffffffffu, v, 1);
    v += __shfl_xor_sync(0xffffffffu, v, 2);
    return v;
}

// ---------------------------------------------------------------------------
// K1/K5: SGEMM tf32, 128x128 tile, BK=16, register-prefetch pipelined
// ---------------------------------------------------------------------------
__global__ __launch_bounds__(256) void sgemm_tf32(
    const float* __restrict__ A, const float* __restrict__ B,
    const float* __restrict__ bias, float* __restrict__ C,
    int M, int N, int K)
{
    __shared__ unsigned As[16][132];
    __shared__ unsigned Bs[16][132];

    int tid = threadIdx.x, lane = tid & 31, wid = tid >> 5;
    int wm = (wid >> 2) * 64, wn = (wid & 3) * 32;
    int m0 = blockIdx.y * 128, n0 = blockIdx.x * 128;
    int grp = lane >> 2, tig = lane & 3;

    float c[4][4][4];
#pragma unroll
    for (int mt = 0; mt < 4; mt++)
#pragma unroll
        for (int nt = 0; nt < 4; nt++)
#pragma unroll
            for (int i = 0; i < 4; i++) c[mt][nt][i] = 0.f;

    int ar = tid >> 1, ac = (tid & 1) * 8;
    int bk = tid >> 4, bn = (tid & 15) * 8;
    const float* Ap = A + (size_t)(m0 + ar) * K + ac;
    const float* Bp = B + (size_t)bk * N + n0 + bn;

    float4 pa0 = *(const float4*)(Ap);
    float4 pa1 = *(const float4*)(Ap + 4);
    float4 pb0 = *(const float4*)(Bp);
    float4 pb1 = *(const float4*)(Bp + 4);

    for (int k0 = 0; k0 < K; k0 += 16) {
        As[ac + 0][ar] = f2tf32(pa0.x); As[ac + 1][ar] = f2tf32(pa0.y);
        As[ac + 2][ar] = f2tf32(pa0.z); As[ac + 3][ar] = f2tf32(pa0.w);
        As[ac + 4][ar] = f2tf32(pa1.x); As[ac + 5][ar] = f2tf32(pa1.y);
        As[ac + 6][ar] = f2tf32(pa1.z); As[ac + 7][ar] = f2tf32(pa1.w);
        uint4 u0 = make_uint4(f2tf32(pb0.x), f2tf32(pb0.y), f2tf32(pb0.z), f2tf32(pb0.w));
        uint4 u1 = make_uint4(f2tf32(pb1.x), f2tf32(pb1.y), f2tf32(pb1.z), f2tf32(pb1.w));
        *(uint4*)&Bs[bk][bn]     = u0;
        *(uint4*)&Bs[bk][bn + 4] = u1;
        __syncthreads();

        if (k0 + 16 < K) {
            pa0 = *(const float4*)(Ap + k0 + 16);
            pa1 = *(const float4*)(Ap + k0 + 20);
            const float* bp = Bp + (size_t)(k0 + 16) * N;
            pb0 = *(const float4*)(bp);
            pb1 = *(const float4*)(bp + 4);
        }

#pragma unroll
        for (int ks = 0; ks < 2; ks++) {
            int kb = ks * 8;
            unsigned af[4][4], bf[4][2];
#pragma unroll
            for (int mt = 0; mt < 4; mt++) {
                int row = wm + mt * 16 + grp;
                af[mt][0] = As[kb + tig][row];
                af[mt][1] = As[kb + tig][row + 8];
                af[mt][2] = As[kb + tig + 4][row];
                af[mt][3] = As[kb + tig + 4][row + 8];
            }
#pragma unroll
            for (int nt = 0; nt < 4; nt++) {
                int col = wn + nt * 8 + grp;
                bf[nt][0] = Bs[kb + tig][col];
                bf[nt][1] = Bs[kb + tig + 4][col];
            }
#pragma unroll
            for (int mt = 0; mt < 4; mt++)
#pragma unroll
                for (int nt = 0; nt < 4; nt++)
                    mma16n8k8(c[mt][nt], af[mt], bf[nt]);
        }
        __syncthreads();
    }

#pragma unroll
    for (int mt = 0; mt < 4; mt++) {
        int r0 = m0 + wm + mt * 16 + grp;
#pragma unroll
        for (int nt = 0; nt < 4; nt++) {
            int col = n0 + wn + nt * 8 + tig * 2;
            float2 bv = *(const float2*)(bias + col);
            *(float2*)(C + (size_t)r0 * N + col) =
                make_float2(c[mt][nt][0] + bv.x, c[mt][nt][1] + bv.y);
            *(float2*)(C + (size_t)(r0 + 8) * N + col) =
                make_float2(c[mt][nt][2] + bv.x, c[mt][nt][3] + bv.y);
        }
    }
}

// ---------------------------------------------------------------------------
// Fused attention: scores + softmax + AV in one kernel.
// Block = (bh, 128 q rows). Warp w owns q rows [w*16, w*16+16).
// Pass 1: stream K tiles (64 rows), S=Q.K^T via mma, online row (max,sumexp).
// Pass 2: recompute S, p=exp(s-m)/l -> write attn_weights, AV mma via
//         shfl-permuted fragments (C-layout -> A-layout), accumulate O.
// Q is pre-scaled by 0.125 (exact) and held as A-fragments in registers.
// ---------------------------------------------------------------------------
__global__ __launch_bounds__(256, 2) void attn_fused(
    const float* __restrict__ qkv, float* __restrict__ w,
    float* __restrict__ ctx)
{
    __shared__ unsigned Ks[64][68];   // [k-row][d]  (68%32==4 -> cf frags)
    __shared__ unsigned Vs[64][72];   // [k-row][d]  (72%32==8 -> cf frags)

    int tid = threadIdx.x, lane = tid & 31, wid = tid >> 5;
    int grp = lane >> 2, tig = lane & 3;
    int qt = 7 - blockIdx.x;          // heavy tiles first
    int q0 = qt * 128;
    int ntiles = qt * 2 + 2;          // k-tiles of 64 covering [0, q0+128)
    int bh = blockIdx.y;
    int b = bh >> 4, h = bh & 15;

    int row0 = wid * 16 + grp;        // local q row (and +8)
    int gq0 = q0 + row0, gq1 = gq0 + 8;

    // --- Q as register A-fragments (scaled by 1/8, exact) ---
    const float* Q0 = qkv + (size_t)(b * PS + gq0) * QKV_N + h * PHD;
    const float* Q1 = Q0 + 8 * QKV_N;
    unsigned qa[8][4];
#pragma unroll
    for (int kd = 0; kd < 8; kd++) {
        qa[kd][0] = f2tf32(Q0[kd * 8 + tig] * 0.125f);
        qa[kd][1] = f2tf32(Q1[kd * 8 + tig] * 0.125f);
        qa[kd][2] = f2tf32(Q0[kd * 8 + tig + 4] * 0.125f);
        qa[kd][3] = f2tf32(Q1[kd * 8 + tig + 4] * 0.125f);
    }

    int kr = tid >> 2, kc = (tid & 3) * 16;   // staging: 64 rows x 64 cols
    const float* Kb = qkv + (size_t)(b * PS + kr) * QKV_N + PD + h * PHD + kc;
    const float* Vb = Kb + PD;

    float m0 = -INFINITY, m1 = -INFINITY, l0 = 0.f, l1 = 0.f;

    // ---------------- Pass 1: row stats ----------------
    float4 pk[4];
#pragma unroll
    for (int i = 0; i < 4; i++) pk[i] = *(const float4*)(Kb + i * 4);

    for (int t = 0; t < ntiles; t++) {
#pragma unroll
        for (int i = 0; i < 4; i++) {
            Ks[kr][kc + i * 4 + 0] = f2tf32(pk[i].x);
            Ks[kr][kc + i * 4 + 1] = f2tf32(pk[i].y);
            Ks[kr][kc + i * 4 + 2] = f2tf32(pk[i].z);
            Ks[kr][kc + i * 4 + 3] = f2tf32(pk[i].w);
        }
        __syncthreads();
        if (t + 1 < ntiles) {
#pragma unroll
            for (int i = 0; i < 4; i++)
                pk[i] = *(const float4*)(Kb + (size_t)(t + 1) * 64 * QKV_N + i * 4);
        }

        float c[8][4];
#pragma unroll
        for (int nt = 0; nt < 8; nt++)
#pragma unroll
            for (int i = 0; i < 4; i++) c[nt][i] = 0.f;
#pragma unroll
        for (int kd = 0; kd < 8; kd++) {
            int kb = kd * 8;
#pragma unroll
            for (int nt = 0; nt < 8; nt++) {
                unsigned bf[2] = { Ks[nt * 8 + grp][kb + tig],
                                   Ks[nt * 8 + grp][kb + tig + 4] };
                mma16n8k8(c[nt], qa[kd], bf);
            }
        }

        int kt0 = t * 64;
        if (t + 2 >= ntiles) {   // diagonal tiles: mask col > row
#pragma unroll
            for (int nt = 0; nt < 8; nt++) {
                int cc = kt0 + nt * 8 + tig * 2;
                if (cc > gq0)     c[nt][0] = -INFINITY;
                if (cc + 1 > gq0) c[nt][1] = -INFINITY;
                if (cc > gq1)     c[nt][2] = -INFINITY;
                if (cc + 1 > gq1) c[nt][3] = -INFINITY;
            }
        }

        float tm0 = -INFINITY, tm1 = -INFINITY;
#pragma unroll
        for (int nt = 0; nt < 8; nt++) {
            tm0 = fmaxf(tm0, fmaxf(c[nt][0], c[nt][1]));
            tm1 = fmaxf(tm1, fmaxf(c[nt][2], c[nt][3]));
        }
        tm0 = qmax(tm0); tm1 = qmax(tm1);
        float nm0 = fmaxf(m0, tm0), nm1 = fmaxf(m1, tm1);
        float s0 = 0.f, s1 = 0.f;
#pragma unroll
        for (int nt = 0; nt < 8; nt++) {
            s0 += __expf(c[nt][0] - nm0) + __expf(c[nt][1] - nm0);
            s1 += __expf(c[nt][2] - nm1) + __expf(c[nt][3] - nm1);
        }
        s0 = qsum(s0); s1 = qsum(s1);
        l0 = l0 * __expf(m0 - nm0) + s0;
        l1 = l1 * __expf(m1 - nm1) + s1;
        m0 = nm0; m1 = nm1;
        __syncthreads();
    }

    float inv0 = 1.f / l0, inv1 = 1.f / l1;

    // ---------------- Pass 2: emit weights + AV ----------------
    float o[8][4];
#pragma unroll
    for (int nt = 0; nt < 8; nt++)
#pragma unroll
        for (int i = 0; i < 4; i++) o[nt][i] = 0.f;

    float* wr0 = w + (size_t)(bh * PS + gq0) * PS;
    float* wr1 = wr0 + 8 * PS;
    int base = lane & ~3;

    for (int t = 0; t < ntiles; t++) {
#pragma unroll
        for (int i = 0; i < 4; i++) {
            float4 kv = *(const float4*)(Kb + (size_t)t * 64 * QKV_N + i * 4);
            float4 vv = *(const float4*)(Vb + (size_t)t * 64 * QKV_N + i * 4);
            Ks[kr][kc + i * 4 + 0] = f2tf32(kv.x);
            Ks[kr][kc + i * 4 + 1] = f2tf32(kv.y);
            Ks[kr][kc + i * 4 + 2] = f2tf32(kv.z);
            Ks[kr][kc + i * 4 + 3] = f2tf32(kv.w);
            Vs[kr][kc + i * 4 + 0] = f2tf32(vv.x);
            Vs[kr][kc + i * 4 + 1] = f2tf32(vv.y);
            Vs[kr][kc + i * 4 + 2] = f2tf32(vv.z);
            Vs[kr][kc + i * 4 + 3] = f2tf32(vv.w);
        }
        __syncthreads();

        float c[8][4];
#pragma unroll
        for (int nt = 0; nt < 8; nt++)
#pragma unroll
            for (int i = 0; i < 4; i++) c[nt][i] = 0.f;
#pragma unroll
        for (int kd = 0; kd < 8; kd++) {
            int kb = kd * 8;
#pragma unroll
            for (int nt = 0; nt < 8; nt++) {
                unsigned bf[2] = { Ks[nt * 8 + grp][kb + tig],
                                   Ks[nt * 8 + grp][kb + tig + 4] };
                mma16n8k8(c[nt], qa[kd], bf);
            }
        }

        int kt0 = t * 64;
        bool diag = (t + 2 >= ntiles);

#pragma unroll
        for (int nt = 0; nt < 8; nt++) {
            int cc = kt0 + nt * 8 + tig * 2;
            float p0 = __expf(c[nt][0] - m0) * inv0;
            float p1 = __expf(c[nt][1] - m0) * inv0;
            float p2 = __expf(c[nt][2] - m1) * inv1;
            float p3 = __expf(c[nt][3] - m1) * inv1;
            if (diag) {
                if (cc > gq0)     p0 = 0.f;
                if (cc + 1 > gq0) p1 = 0.f;
                if (cc > gq1)     p2 = 0.f;
                if (cc + 1 > gq1) p3 = 0.f;
            }
            *(float2*)(wr0 + cc) = make_float2(p0, p1);
            *(float2*)(wr1 + cc) = make_float2(p2, p3);

            // C-layout -> A-layout permute (intra-quad shfls)
            unsigned u0 = f2tf32(p0), u1 = f2tf32(p1);
            unsigned u2 = f2tf32(p2), u3 = f2tf32(p3);
            int s0l = base + (tig >> 1);
            int s1l = s0l + 2;
            unsigned e0 = __shfl_sync(0xffffffffu, u0, s0l);
            unsigned f0 = __shfl_sync(0xffffffffu, u1, s0l);
            unsigned e1 = __shfl_sync(0xffffffffu, u2, s0l);
            unsigned f1 = __shfl_sync(0xffffffffu, u3, s0l);
            unsigned e2 = __shfl_sync(0xffffffffu, u0, s1l);
            unsigned f2 = __shfl_sync(0xffffffffu, u1, s1l);
            unsigned e3 = __shfl_sync(0xffffffffu, u2, s1l);
            unsigned f3 = __shfl_sync(0xffffffffu, u3, s1l);
            bool odd = (tig & 1);
            unsigned a[4];
            a[0] = odd ? f0 : e0;
            a[1] = odd ? f1 : e1;
            a[2] = odd ? f2 : e2;
            a[3] = odd ? f3 : e3;

#pragma unroll
            for (int ntd = 0; ntd < 8; ntd++) {
                unsigned bf[2] = { Vs[nt * 8 + tig][ntd * 8 + grp],
                                   Vs[nt * 8 + tig + 4][ntd * 8 + grp] };
                mma16n8k8(o[ntd], a, bf);
            }
        }
        __syncthreads();
    }

    // ctx epilogue
    float* c0p = ctx + (size_t)(b * PS + gq0) * PD + h * PHD;
    float* c1p = c0p + 8 * PD;
#pragma unroll
    for (int ntd = 0; ntd < 8; ntd++) {
        int col = ntd * 8 + tig * 2;
        *(float2*)(c0p + col) = make_float2(o[ntd][0], o[ntd][1]);
        *(float2*)(c1p + col) = make_float2(o[ntd][2], o[ntd][3]);
    }

    // zero-fill strictly-upper region cols [q0+128, 1024)
    int zc = q0 + 128;
    int nz4 = (PS - zc) >> 2;
    if (nz4 > 0) {
        float4 z = make_float4(0.f, 0.f, 0.f, 0.f);
        for (int i = tid; i < 128 * nz4; i += 256) {
            int r = i / nz4, c4 = i - r * nz4;
            *(float4*)(w + (size_t)(bh * PS + q0 + r) * PS + zc + c4 * 4) = z;
        }
    }
}

// ---------------------------------------------------------------------------
extern "C" void kernel_launch(void* const* d_in, const int* in_sizes, int n_in,
                              void* d_out, int out_size)
{
    const float* hidden = (const float*)d_in[0];
    const float* W_attn = (const float*)d_in[1];
    const float* b_attn = (const float*)d_in[2];
    const float* W_proj = (const float*)d_in[3];
    const float* b_proj = (const float*)d_in[4];
    float* out = (float*)d_out;

    float *qkv, *ctx, *wscr;
    cudaGetSymbolAddress((void**)&qkv, g_qkv);
    cudaGetSymbolAddress((void**)&ctx, g_ctx);
    cudaGetSymbolAddress((void**)&wscr, g_wscratch);

    float* attn_out = out;
    float* wptr;
    if ((unsigned long long)out_size >= ATTN_OUT_ELEMS + ATTN_W_ELEMS) {
        wptr = out + ATTN_OUT_ELEMS;
    } else if ((unsigned long long)out_size == ATTN_W_ELEMS) {
        wptr = out;
        attn_out = ctx;
    } else {
        wptr = wscr;
    }

    // K1: QKV projection
    sgemm_tf32<<<dim3(QKV_N / 128, BS / 128), 256>>>(
        hidden, W_attn, b_attn, qkv, BS, QKV_N, PD);

    // K2: fused scores + softmax + AV
    attn_fused<<<dim3(8, PB * PH), 256>>>(qkv, wptr, ctx);

    // K3: output projection
    sgemm_tf32<<<dim3(PD / 128, BS / 128), 256>>>(
        ctx, W_proj, b_proj, attn_out, BS, PD, PD);
}